// round 3
// baseline (speedup 1.0000x reference)
#include <cuda_runtime.h>

#define MDIM 1024
#define GR   16            // rows per block = 8 warps x 2 rows
#define TPB  256
#define PAIRSTRIDE (3*MDIM*2)                      // floats per row-pair buffer
#define SMEM_BYTES (8*PAIRSTRIDE*4 + MDIM*16 + MDIM*16)   // 196608+16384+16384 = 229376

// ---------------- schedule scratch (no allocations allowed) ----------------
__device__ int    d_off[MDIM + 2];
__device__ int4   d_pidx[MDIM];    // level-sorted parent tuples (a0,a1,p0,p1)
__device__ float4 d_pw[MDIM];      // level-sorted (-w0*log2e, -w1*log2e, -b*log2e, step-id bits)
__device__ int    d_nlev;

// ---------------------------------------------------------------------------
// Kernel 1: exact dataflow levels via warp-serial chunk pass (32 chunks of 32
// steps; parents are strictly lower-indexed, so earlier chunks are final and
// intra-chunk chains resolve with a few shuffle iterations). Then counting
// sort by level with a warp-scan for offsets. ~4 block barriers total.
// ---------------------------------------------------------------------------
__global__ void sched_kernel(const int* __restrict__ raw,
                             const float* __restrict__ W_sig,
                             const float* __restrict__ b_sig) {
    __shared__ int lvl[MDIM];
    __shared__ int cnt[MDIM];
    __shared__ int cur[MDIM];
    __shared__ int s_max;

    int i = threadIdx.x;
    cnt[i] = 0;
    if (i == 0) s_max = 0;
    __syncthreads();

    if (i < 32) {
        int lane = i;
        for (int c = 0; c < MDIM/32; c++) {
            int idx  = c*32 + lane;
            int base = c*32;
            int q0 = raw[2*idx],        q1 = raw[2*idx + 1];
            int q2 = raw[2*MDIM + 2*idx], q3 = raw[2*MDIM + 2*idx + 1];
            int l = 0;
            int e0 = -1, e1 = -1, e2 = -1, e3 = -1;   // in-chunk parent lanes
            if (q0 >= MDIM) { int pc = q0 & (MDIM-1); if (pc < base) l = max(l, lvl[pc]+1); else e0 = pc - base; }
            if (q1 >= MDIM) { int pc = q1 & (MDIM-1); if (pc < base) l = max(l, lvl[pc]+1); else e1 = pc - base; }
            if (q2 >= MDIM) { int pc = q2 & (MDIM-1); if (pc < base) l = max(l, lvl[pc]+1); else e2 = pc - base; }
            if (q3 >= MDIM) { int pc = q3 & (MDIM-1); if (pc < base) l = max(l, lvl[pc]+1); else e3 = pc - base; }
            for (;;) {
                int v0 = __shfl_sync(0xffffffffu, l, e0 < 0 ? 0 : e0);
                int v1 = __shfl_sync(0xffffffffu, l, e1 < 0 ? 0 : e1);
                int v2 = __shfl_sync(0xffffffffu, l, e2 < 0 ? 0 : e2);
                int v3 = __shfl_sync(0xffffffffu, l, e3 < 0 ? 0 : e3);
                int nl = l;
                if (e0 >= 0) nl = max(nl, v0 + 1);
                if (e1 >= 0) nl = max(nl, v1 + 1);
                if (e2 >= 0) nl = max(nl, v2 + 1);
                if (e3 >= 0) nl = max(nl, v3 + 1);
                unsigned ch = __ballot_sync(0xffffffffu, nl != l);
                l = nl;
                if (!ch) break;
            }
            lvl[idx] = l;
        }
    }
    __syncthreads();

    int L = lvl[i];
    atomicAdd(&cnt[L], 1);
    atomicMax(&s_max, L);
    __syncthreads();

    if (i < 32) {                        // warp-scan counts -> exclusive offsets
        int carry = 0;
        for (int b = 0; b < MDIM; b += 32) {
            int v = cnt[b + i];
            int s = v;
            #pragma unroll
            for (int o = 1; o < 32; o <<= 1) {
                int t = __shfl_up_sync(0xffffffffu, s, o);
                if (i >= o) s += t;
            }
            int excl = carry + s - v;
            d_off[b + i] = excl;
            cur[b + i]   = excl;
            carry += __shfl_sync(0xffffffffu, s, 31);
        }
        if (i == 0) { d_off[MDIM] = MDIM; d_off[MDIM+1] = MDIM; d_nlev = s_max + 1; }
    }
    __syncthreads();

    // scatter packed schedule (within-level order arbitrary)
    int p0 = raw[2*i],          p1 = raw[2*i + 1];
    int p2 = raw[2*MDIM + 2*i], p3 = raw[2*MDIM + 2*i + 1];
    int pos = atomicAdd(&cur[L], 1);
    d_pidx[pos] = make_int4(p0, p1, p2, p3);
    const float NL2E = -1.4426950408889634f;     // fold -z*log2e into weights
    float4 w;
    w.x = W_sig[2*i] * NL2E; w.y = W_sig[2*i + 1] * NL2E; w.z = b_sig[i] * NL2E;
    w.w = __int_as_float(i);
    d_pw[pos] = w;
}

// ---------------------------------------------------------------------------
__device__ __forceinline__ float sigmoid_fold(float t) {   // t = -z*log2e
    float e, p;
    asm("ex2.approx.f32 %0, %1;" : "=f"(e) : "f"(t));
    asm("rcp.approx.f32 %0, %1;" : "=f"(p) : "f"(1.0f + e));
    return p;
}

// ---------------------------------------------------------------------------
// Kernel 2: one WARP owns a PAIR of rows. Lanes = 16 steps x 2 rows; pair
// buffer interleaved pb[value*2 + r] so each gather LDS carries both rows with
// all 32 lanes useful (2x fewer smem wavefronts per row than 1-row/warp).
// Row data is warp-private: zero block-wide barriers in the main loop.
// ---------------------------------------------------------------------------
__global__ void __launch_bounds__(TPB, 1)
tree_kernel(const float* __restrict__ x,
            const float* __restrict__ W_base, const float* __restrict__ b_base,
            const float* __restrict__ w_plus, const float* __restrict__ b_plus,
            const float* __restrict__ w_prod, const float* __restrict__ b_prod,
            float* __restrict__ out, int nGroups)
{
    extern __shared__ char smraw[];
    float*  buf  = (float*)smraw;                              // [8][PAIRSTRIDE]
    int4*   sIdx = (int4*) (smraw + 8*PAIRSTRIDE*4);           // [M]
    float4* sW   = (float4*)(smraw + 8*PAIRSTRIDE*4 + MDIM*16);// [M]

    int tid  = threadIdx.x;
    int lane = tid & 31;
    int w    = tid >> 5;                 // warp id = pair index (0..7)

    for (int i = tid; i < MDIM; i += TPB) { sIdx[i] = d_pidx[i]; sW[i] = d_pw[i]; }
    __syncthreads();                     // the ONLY block-wide barrier

    const int nLev = d_nlev;
    float* pb = buf + w * PAIRSTRIDE;
    float bias = b_base[0] + b_plus[0] + b_prod[0];

    int r  = lane & 1;                   // row-within-pair for the level loop
    int sl = lane >> 1;                  // step slot (0..15)

    for (int grp = blockIdx.x; grp < nGroups; grp += gridDim.x) {
        int rowBase = grp * GR;

        // stage this warp's 2 rows of x into interleaved layout (coalesced LDG)
        {
            int rr = lane >> 4, lh = lane & 15;
            const float4* xr = (const float4*)(x + (size_t)(rowBase + 2*w + rr) * MDIM);
            #pragma unroll
            for (int k = 0; k < 16; k++) {
                float4 a = xr[k*16 + lh];
                int m = k*64 + lh*4;
                pb[(m+0)*2 + rr] = a.x;
                pb[(m+1)*2 + rr] = a.y;
                pb[(m+2)*2 + rr] = a.z;
                pb[(m+3)*2 + rr] = a.w;
            }
        }
        __syncwarp();

        // level-parallel recurrence; first chunk of next level prefetched
        int s0 = 0;
        int s1 = d_off[1];
        int4 v; float4 wv;
        if (sl < s1) { v = sIdx[sl]; wv = sW[sl]; }

        for (int L = 0; L < nLev; L++) {
            int s2 = d_off[L + 2];               // off the critical path
            int n = s1 - s0;
            if (sl < n) {                        // chunk 0 (prefetched)
                float a0 = pb[v.x*2 + r], a1 = pb[v.y*2 + r];
                float b0 = pb[v.z*2 + r], b1 = pb[v.w*2 + r];
                float t  = fmaf(wv.x, a0, fmaf(wv.y, a1, wv.z));
                int s = __float_as_int(wv.w);
                pb[(2*MDIM + s)*2 + r] = b0 * b1;          // prod (off chain)
                pb[(MDIM   + s)*2 + r] = sigmoid_fold(t);  // plus
            }
            for (int cb = s0 + 16; cb < s1; cb += 16) {    // rare spill chunks
                int sp = cb + sl;
                if (sp < s1) {
                    int4 v2 = sIdx[sp]; float4 w2 = sW[sp];
                    float a0 = pb[v2.x*2 + r], a1 = pb[v2.y*2 + r];
                    float b0 = pb[v2.z*2 + r], b1 = pb[v2.w*2 + r];
                    float t  = fmaf(w2.x, a0, fmaf(w2.y, a1, w2.z));
                    int s = __float_as_int(w2.w);
                    pb[(2*MDIM + s)*2 + r] = b0 * b1;
                    pb[(MDIM   + s)*2 + r] = sigmoid_fold(t);
                }
            }
            { int sp = s1 + sl; if (sp < s2) { v = sIdx[sp]; wv = sW[sp]; } }
            __syncwarp();
            s0 = s1; s1 = s2;
        }

        // epilogue: both rows' triple dot products via float2 LDS (conflict-free)
        float accx = 0.f, accy = 0.f;
        for (int m = lane; m < MDIM; m += 32) {
            float2 xv = *(const float2*)&pb[m*2];
            float2 pv = *(const float2*)&pb[(MDIM   + m)*2];
            float2 qv = *(const float2*)&pb[(2*MDIM + m)*2];
            float wb = W_base[m], wp = w_plus[m], wq = w_prod[m];
            accx = fmaf(xv.x, wb, fmaf(pv.x, wp, fmaf(qv.x, wq, accx)));
            accy = fmaf(xv.y, wb, fmaf(pv.y, wp, fmaf(qv.y, wq, accy)));
        }
        #pragma unroll
        for (int o = 16; o; o >>= 1) {
            accx += __shfl_xor_sync(0xffffffffu, accx, o);
            accy += __shfl_xor_sync(0xffffffffu, accy, o);
        }
        if (lane == 0) {
            out[rowBase + 2*w]     = accx + bias;
            out[rowBase + 2*w + 1] = accy + bias;
        }
        __syncwarp();    // pair buffer is warp-private; safe to restage
    }
}

// ---------------------------------------------------------------------------
extern "C" void kernel_launch(void* const* d_in, const int* in_sizes, int n_in,
                              void* d_out, int out_size) {
    const float* x  = (const float*)d_in[0];
    const int*   ri = (const int*)  d_in[1];
    const float* Wb = (const float*)d_in[2];
    const float* bb = (const float*)d_in[3];
    const float* Ws = (const float*)d_in[4];
    const float* bs = (const float*)d_in[5];
    const float* wp = (const float*)d_in[6];
    const float* bp = (const float*)d_in[7];
    const float* wq = (const float*)d_in[8];
    const float* bq = (const float*)d_in[9];
    float* out = (float*)d_out;

    int B = in_sizes[0] / MDIM;          // 8192
    int nGroups = B / GR;                // 512

    static int sm_count = 0;
    if (sm_count == 0) {
        int dev = 0;
        cudaGetDevice(&dev);
        cudaDeviceGetAttribute(&sm_count, cudaDevAttrMultiProcessorCount, dev);
        if (sm_count <= 0) sm_count = 148;
        cudaFuncSetAttribute(tree_kernel,
                             cudaFuncAttributeMaxDynamicSharedMemorySize, SMEM_BYTES);
    }
    int grid = nGroups < sm_count ? nGroups : sm_count;

    sched_kernel<<<1, MDIM>>>(ri, Ws, bs);
    tree_kernel<<<grid, TPB, SMEM_BYTES>>>(x, Wb, bb, wp, bp, wq, bq, out, nGroups);
}

// round 4
// speedup vs baseline: 1.3685x; 1.3685x over previous
#include <cuda_runtime.h>

#define MDIM 1024
#define GR   16                 // rows per block = warps per block
#define TPB  512
#define ROWSTRIDE (3*MDIM)

// shared layout: row buffers | packed schedule | epilogue weights | level offsets
#define BUF_BYTES  (GR*ROWSTRIDE*4)            // 196608
#define SIDX_OFF   (BUF_BYTES)                 // short4[M]  (remapped parents)  8192
#define SWT_OFF    (SIDX_OFF + MDIM*8)         // float4[M]  (w0',w1',b',-)     16384
#define WEPI_OFF   (SWT_OFF  + MDIM*16)        // float2[M]  (wp',wq')           8192
#define OFFS_OFF   (WEPI_OFF + MDIM*8)         // short[1026] level offsets      2056
#define SMEM_BYTES (OFFS_OFF + 2056)           // 231432  (<= 232448 cap)

__device__ __forceinline__ float sigmoid_fold(float t) {   // t = -z*log2e
    float e, p;
    asm("ex2.approx.f32 %0, %1;" : "=f"(e) : "f"(t));
    asm("rcp.approx.f32 %0, %1;" : "=f"(p) : "f"(1.0f + e));
    return p;
}

// ---------------------------------------------------------------------------
// Single fused kernel.
//  Setup (per block, scratch overlaid on the row-buffer region):
//   - stage raw parents, compute exact DAG levels (warp-0 chunk relaxation),
//     counting-sort by level, REMAP ids to schedule order (stores contiguous),
//     emit packed schedule: short4 parents + float4 folded sigmoid weights +
//     permuted epilogue weights.
//  Main: one WARP owns one row end-to-end in smem [x|plus|prod] (12KB).
//   Zero block-wide barriers; per-level __syncwarp with next-level prefetch.
// ---------------------------------------------------------------------------
__global__ void __launch_bounds__(TPB, 1)
tree_kernel(const float* __restrict__ x,      const int* __restrict__ raw,
            const float* __restrict__ W_base, const float* __restrict__ b_base,
            const float* __restrict__ W_sig,  const float* __restrict__ b_sig,
            const float* __restrict__ w_plus, const float* __restrict__ b_plus,
            const float* __restrict__ w_prod, const float* __restrict__ b_prod,
            float* __restrict__ out, int nGroups)
{
    extern __shared__ char smraw[];
    float*  buf  = (float*) smraw;                       // [GR][3*M]
    short4* sIdx = (short4*)(smraw + SIDX_OFF);          // [M]
    float4* sWt  = (float4*)(smraw + SWT_OFF);           // [M]
    float2* wepi = (float2*)(smraw + WEPI_OFF);          // [M]
    short*  offs = (short*) (smraw + OFFS_OFF);          // [1026]

    // setup scratch overlaid on buf (released before staging rows)
    short4* sP   = (short4*)smraw;                       // [M] raw parents
    int*    lvl  = (int*)(smraw + 8192);                 // [M]
    int*    cnt  = (int*)(smraw + 12288);                // [M]
    int*    cur  = (int*)(smraw + 16384);                // [M]
    int*    posA = (int*)(smraw + 20480);                // [M]

    int tid  = threadIdx.x;
    int lane = tid & 31;
    int wid  = tid >> 5;

    // ---- Phase 0: stage parents, zero counters -----------------------------
    for (int i = tid; i < MDIM; i += TPB) {
        short4 p;
        p.x = (short)raw[2*i];          p.y = (short)raw[2*i + 1];
        p.z = (short)raw[2*MDIM + 2*i]; p.w = (short)raw[2*MDIM + 2*i + 1];
        sP[i] = p;
        cnt[i] = 0;
    }
    __syncthreads();

    // ---- Phase 1: exact levels, warp-0 serial over 32-step chunks ----------
    if (wid == 0) {
        for (int c = 0; c < MDIM/32; c++) {
            int idx  = c*32 + lane;
            int base = c*32;
            short4 p = sP[idx];
            int l = 0;
            int e0 = -1, e1 = -1, e2 = -1, e3 = -1;
            int q;
            q = p.x; if (q >= MDIM) { int pc = q & (MDIM-1); if (pc < base) l = max(l, lvl[pc]+1); else e0 = pc - base; }
            q = p.y; if (q >= MDIM) { int pc = q & (MDIM-1); if (pc < base) l = max(l, lvl[pc]+1); else e1 = pc - base; }
            q = p.z; if (q >= MDIM) { int pc = q & (MDIM-1); if (pc < base) l = max(l, lvl[pc]+1); else e2 = pc - base; }
            q = p.w; if (q >= MDIM) { int pc = q & (MDIM-1); if (pc < base) l = max(l, lvl[pc]+1); else e3 = pc - base; }
            for (;;) {
                int v0 = __shfl_sync(0xffffffffu, l, e0 < 0 ? 0 : e0);
                int v1 = __shfl_sync(0xffffffffu, l, e1 < 0 ? 0 : e1);
                int v2 = __shfl_sync(0xffffffffu, l, e2 < 0 ? 0 : e2);
                int v3 = __shfl_sync(0xffffffffu, l, e3 < 0 ? 0 : e3);
                int nl = l;
                if (e0 >= 0) nl = max(nl, v0 + 1);
                if (e1 >= 0) nl = max(nl, v1 + 1);
                if (e2 >= 0) nl = max(nl, v2 + 1);
                if (e3 >= 0) nl = max(nl, v3 + 1);
                unsigned ch = __ballot_sync(0xffffffffu, nl != l);
                l = nl;
                if (!ch) break;
            }
            lvl[idx] = l;
        }
    }
    __syncthreads();

    // ---- Phase 2: histogram levels ----------------------------------------
    for (int i = tid; i < MDIM; i += TPB) atomicAdd(&cnt[lvl[i]], 1);
    __syncthreads();

    // ---- Phase 3: warp-0 scan -> level offsets ----------------------------
    if (wid == 0) {
        int carry = 0;
        for (int b = 0; b < MDIM; b += 32) {
            int v = cnt[b + lane];
            int s = v;
            #pragma unroll
            for (int o = 1; o < 32; o <<= 1) {
                int t = __shfl_up_sync(0xffffffffu, s, o);
                if (lane >= o) s += t;
            }
            int excl = carry + s - v;
            offs[b + lane] = (short)excl;
            cur[b + lane]  = excl;
            carry += __shfl_sync(0xffffffffu, s, 31);
        }
        if (lane == 0) { offs[MDIM] = MDIM; offs[MDIM+1] = MDIM; }
    }
    __syncthreads();

    // ---- Phase 4: schedule position of every step -------------------------
    for (int i = tid; i < MDIM; i += TPB) posA[i] = atomicAdd(&cur[lvl[i]], 1);
    __syncthreads();

    // ---- Phase 5: emit remapped packed schedule ---------------------------
    const float NL2E = -1.4426950408889634f;
    for (int i = tid; i < MDIM; i += TPB) {
        short4 p = sP[i];
        int pos = posA[i];
        short4 v;
        int q;
        q = p.x; v.x = (short)(q < MDIM ? q : (q < 2*MDIM ? MDIM + posA[q - MDIM] : 2*MDIM + posA[q - 2*MDIM]));
        q = p.y; v.y = (short)(q < MDIM ? q : (q < 2*MDIM ? MDIM + posA[q - MDIM] : 2*MDIM + posA[q - 2*MDIM]));
        q = p.z; v.z = (short)(q < MDIM ? q : (q < 2*MDIM ? MDIM + posA[q - MDIM] : 2*MDIM + posA[q - 2*MDIM]));
        q = p.w; v.w = (short)(q < MDIM ? q : (q < 2*MDIM ? MDIM + posA[q - MDIM] : 2*MDIM + posA[q - 2*MDIM]));
        sIdx[pos] = v;
        float4 w;
        w.x = W_sig[2*i] * NL2E; w.y = W_sig[2*i + 1] * NL2E; w.z = b_sig[i] * NL2E; w.w = 0.f;
        sWt[pos] = w;
        wepi[pos] = make_float2(w_plus[i], w_prod[i]);
    }
    __syncthreads();                     // last block-wide barrier

    // ---- Main: one warp per row, persistent over groups -------------------
    float* rb = buf + wid * ROWSTRIDE;
    float bias = b_base[0] + b_plus[0] + b_prod[0];

    for (int grp = blockIdx.x; grp < nGroups; grp += gridDim.x) {
        int row = grp * GR + wid;

        // stage x (coalesced float4) and fold x . W_base on the fly
        const float4* xr = (const float4*)(x + (size_t)row * MDIM);
        const float4* wb4 = (const float4*)W_base;
        float acc = 0.f;
        #pragma unroll
        for (int k = 0; k < MDIM/128; k++) {
            float4 a = xr[lane + 32*k];
            ((float4*)rb)[lane + 32*k] = a;
            float4 wv = wb4[lane + 32*k];
            acc = fmaf(a.x, wv.x, fmaf(a.y, wv.y, fmaf(a.z, wv.z, fmaf(a.w, wv.w, acc))));
        }
        __syncwarp();

        // level loop: stores contiguous at [s0,s1); next level prefetched
        int s0 = 0;
        int s1 = offs[1];
        short4 v; float4 w;
        if (lane < s1) { v = sIdx[lane]; w = sWt[lane]; }

        while (s0 < MDIM) {
            int s2 = offs[(s1 < MDIM) ? 0 : 0], dummy; (void)dummy;
            // (compute next-next offset via level counter-free form below)
            // NOTE: we track level implicitly; offs is indexed by level, so keep L:
            break;
        }
        // -- rewritten with explicit level counter --
        s0 = 0; s1 = offs[1];
        if (lane < s1) { v = sIdx[lane]; w = sWt[lane]; }
        for (int L = 0; s0 < MDIM; L++) {
            int s2 = offs[L + 2];
            int n = s1 - s0;
            if (lane < n) {                       // chunk 0 (prefetched)
                float a0 = rb[v.x], a1 = rb[v.y];
                float b0 = rb[v.z], b1 = rb[v.w];
                float t  = fmaf(w.x, a0, fmaf(w.y, a1, w.z));
                rb[2*MDIM + s0 + lane] = b0 * b1;           // prod (contiguous STS)
                rb[MDIM   + s0 + lane] = sigmoid_fold(t);   // plus
            }
            for (int cb = s0 + 32; cb < s1; cb += 32) {     // rare wide levels
                int sp = cb + lane;
                if (sp < s1) {
                    short4 v2 = sIdx[sp]; float4 w2 = sWt[sp];
                    float a0 = rb[v2.x], a1 = rb[v2.y];
                    float b0 = rb[v2.z], b1 = rb[v2.w];
                    float t  = fmaf(w2.x, a0, fmaf(w2.y, a1, w2.z));
                    rb[2*MDIM + sp] = b0 * b1;
                    rb[MDIM   + sp] = sigmoid_fold(t);
                }
            }
            { int sp = s1 + lane; if (sp < s2) { v = sIdx[sp]; w = sWt[sp]; } }
            __syncwarp();
            s0 = s1; s1 = s2;
        }

        // epilogue: plus/prod dots with permuted weights (stride-32, no conflicts)
        for (int m = lane; m < MDIM; m += 32) {
            float2 we = wepi[m];
            acc = fmaf(rb[MDIM + m], we.x, fmaf(rb[2*MDIM + m], we.y, acc));
        }
        #pragma unroll
        for (int o = 16; o; o >>= 1) acc += __shfl_xor_sync(0xffffffffu, acc, o);
        if (lane == 0) out[row] = acc + bias;
        __syncwarp();
    }
}

// ---------------------------------------------------------------------------
extern "C" void kernel_launch(void* const* d_in, const int* in_sizes, int n_in,
                              void* d_out, int out_size) {
    const float* x  = (const float*)d_in[0];
    const int*   ri = (const int*)  d_in[1];
    const float* Wb = (const float*)d_in[2];
    const float* bb = (const float*)d_in[3];
    const float* Ws = (const float*)d_in[4];
    const float* bs = (const float*)d_in[5];
    const float* wp = (const float*)d_in[6];
    const float* bp = (const float*)d_in[7];
    const float* wq = (const float*)d_in[8];
    const float* bq = (const float*)d_in[9];
    float* out = (float*)d_out;

    int B = in_sizes[0] / MDIM;          // 8192
    int nGroups = B / GR;                // 512

    static int sm_count = 0;
    if (sm_count == 0) {
        int dev = 0;
        cudaGetDevice(&dev);
        cudaDeviceGetAttribute(&sm_count, cudaDevAttrMultiProcessorCount, dev);
        if (sm_count <= 0) sm_count = 148;
        cudaFuncSetAttribute(tree_kernel,
                             cudaFuncAttributeMaxDynamicSharedMemorySize, SMEM_BYTES);
    }
    int grid = nGroups < sm_count ? nGroups : sm_count;

    tree_kernel<<<grid, TPB, SMEM_BYTES>>>(x, ri, Wb, bb, Ws, bs, wp, bp, wq, bq,
                                           out, nGroups);
}

// round 5
// speedup vs baseline: 1.3710x; 1.0018x over previous
#include <cuda_runtime.h>

#define MDIM 1024
#define GR   16                 // rows per block = 8 warps x 2 rows
#define TPB  256
#define ROWSTRIDE (3*MDIM)

// shared layout: row buffers | packed schedule | epilogue weights | level offsets
#define BUF_BYTES  (GR*ROWSTRIDE*4)            // 196608
#define SIDX_OFF   (BUF_BYTES)                 // short4[M] remapped parents     8192
#define SWT_OFF    (SIDX_OFF + MDIM*8)         // float4[M] (w0',w1',b',-)      16384
#define WEPI_OFF   (SWT_OFF  + MDIM*16)        // float2[M] (wp',wq') permuted   8192
#define OFFS_OFF   (WEPI_OFF + MDIM*8)         // short[1026] level offsets      2056
#define SMEM_BYTES (OFFS_OFF + 2056)           // 231432 <= 232448 cap

__device__ __forceinline__ float sigmoid_fold(float t) {   // t = -z*log2e
    float e, p;
    asm("ex2.approx.f32 %0, %1;" : "=f"(e) : "f"(t));
    asm("rcp.approx.f32 %0, %1;" : "=f"(p) : "f"(1.0f + e));
    return p;
}

// ---------------------------------------------------------------------------
// Fused kernel. Per-block setup builds a level-sorted schedule with step ids
// REMAPPED to schedule order (stores contiguous). Main loop: each warp owns
// TWO rows as two separate ILP chains sharing one schedule-register set;
// zero block-wide barriers after setup, per-level __syncwarp only.
// ---------------------------------------------------------------------------
__global__ void __launch_bounds__(TPB, 1)
tree_kernel(const float* __restrict__ x,      const int* __restrict__ raw,
            const float* __restrict__ W_base, const float* __restrict__ b_base,
            const float* __restrict__ W_sig,  const float* __restrict__ b_sig,
            const float* __restrict__ w_plus, const float* __restrict__ b_plus,
            const float* __restrict__ w_prod, const float* __restrict__ b_prod,
            float* __restrict__ out, int nGroups)
{
    extern __shared__ char smraw[];
    float*  buf  = (float*) smraw;                       // [GR][3*M]
    short4* sIdx = (short4*)(smraw + SIDX_OFF);
    float4* sWt  = (float4*)(smraw + SWT_OFF);
    float2* wepi = (float2*)(smraw + WEPI_OFF);
    short*  offs = (short*) (smraw + OFFS_OFF);

    // setup scratch overlaid on buf (released before staging rows)
    short4* sP   = (short4*)smraw;                       // [M] raw parents
    int*    lvl  = (int*)(smraw + 8192);
    int*    cnt  = (int*)(smraw + 12288);
    int*    cur  = (int*)(smraw + 16384);
    int*    posA = (int*)(smraw + 20480);

    int tid  = threadIdx.x;
    int lane = tid & 31;
    int wid  = tid >> 5;

    // ---- Phase 0: stage parents, zero counters ----------------------------
    for (int i = tid; i < MDIM; i += TPB) {
        short4 p;
        p.x = (short)raw[2*i];          p.y = (short)raw[2*i + 1];
        p.z = (short)raw[2*MDIM + 2*i]; p.w = (short)raw[2*MDIM + 2*i + 1];
        sP[i] = p;
        cnt[i] = 0;
    }
    __syncthreads();

    // ---- Phase 1: exact DAG levels, warp 0 over 32-step chunks ------------
    if (wid == 0) {
        for (int c = 0; c < MDIM/32; c++) {
            int idx  = c*32 + lane;
            int base = c*32;
            short4 p = sP[idx];
            int l = 0;
            int e0 = -1, e1 = -1, e2 = -1, e3 = -1;
            int q;
            q = p.x; if (q >= MDIM) { int pc = q & (MDIM-1); if (pc < base) l = max(l, lvl[pc]+1); else e0 = pc - base; }
            q = p.y; if (q >= MDIM) { int pc = q & (MDIM-1); if (pc < base) l = max(l, lvl[pc]+1); else e1 = pc - base; }
            q = p.z; if (q >= MDIM) { int pc = q & (MDIM-1); if (pc < base) l = max(l, lvl[pc]+1); else e2 = pc - base; }
            q = p.w; if (q >= MDIM) { int pc = q & (MDIM-1); if (pc < base) l = max(l, lvl[pc]+1); else e3 = pc - base; }
            for (;;) {
                int v0 = __shfl_sync(0xffffffffu, l, e0 < 0 ? 0 : e0);
                int v1 = __shfl_sync(0xffffffffu, l, e1 < 0 ? 0 : e1);
                int v2 = __shfl_sync(0xffffffffu, l, e2 < 0 ? 0 : e2);
                int v3 = __shfl_sync(0xffffffffu, l, e3 < 0 ? 0 : e3);
                int nl = l;
                if (e0 >= 0) nl = max(nl, v0 + 1);
                if (e1 >= 0) nl = max(nl, v1 + 1);
                if (e2 >= 0) nl = max(nl, v2 + 1);
                if (e3 >= 0) nl = max(nl, v3 + 1);
                unsigned ch = __ballot_sync(0xffffffffu, nl != l);
                l = nl;
                if (!ch) break;
            }
            lvl[idx] = l;
        }
    }
    __syncthreads();

    // ---- Phase 2: level histogram -----------------------------------------
    for (int i = tid; i < MDIM; i += TPB) atomicAdd(&cnt[lvl[i]], 1);
    __syncthreads();

    // ---- Phase 3: warp-0 scan -> level offsets ----------------------------
    if (wid == 0) {
        int carry = 0;
        for (int b = 0; b < MDIM; b += 32) {
            int v = cnt[b + lane];
            int s = v;
            #pragma unroll
            for (int o = 1; o < 32; o <<= 1) {
                int t = __shfl_up_sync(0xffffffffu, s, o);
                if (lane >= o) s += t;
            }
            int excl = carry + s - v;
            offs[b + lane] = (short)excl;
            cur[b + lane]  = excl;
            carry += __shfl_sync(0xffffffffu, s, 31);
        }
        if (lane == 0) { offs[MDIM] = MDIM; offs[MDIM+1] = MDIM; }
    }
    __syncthreads();

    // ---- Phase 4: schedule position of every step -------------------------
    for (int i = tid; i < MDIM; i += TPB) posA[i] = atomicAdd(&cur[lvl[i]], 1);
    __syncthreads();

    // ---- Phase 5: emit remapped packed schedule ---------------------------
    const float NL2E = -1.4426950408889634f;
    for (int i = tid; i < MDIM; i += TPB) {
        short4 p = sP[i];
        int pos = posA[i];
        short4 v;
        int q;
        q = p.x; v.x = (short)(q < MDIM ? q : (q < 2*MDIM ? MDIM + posA[q - MDIM] : 2*MDIM + posA[q - 2*MDIM]));
        q = p.y; v.y = (short)(q < MDIM ? q : (q < 2*MDIM ? MDIM + posA[q - MDIM] : 2*MDIM + posA[q - 2*MDIM]));
        q = p.z; v.z = (short)(q < MDIM ? q : (q < 2*MDIM ? MDIM + posA[q - MDIM] : 2*MDIM + posA[q - 2*MDIM]));
        q = p.w; v.w = (short)(q < MDIM ? q : (q < 2*MDIM ? MDIM + posA[q - MDIM] : 2*MDIM + posA[q - 2*MDIM]));
        sIdx[pos] = v;
        float4 w;
        w.x = W_sig[2*i] * NL2E; w.y = W_sig[2*i + 1] * NL2E; w.z = b_sig[i] * NL2E; w.w = 0.f;
        sWt[pos] = w;
        wepi[pos] = make_float2(w_plus[i], w_prod[i]);
    }
    __syncthreads();                     // last block-wide barrier

    // ---- Main: each warp owns 2 rows (two ILP chains, shared schedule) ----
    float* rbA = buf + (2*wid)     * ROWSTRIDE;
    float* rbB = buf + (2*wid + 1) * ROWSTRIDE;
    float bias = b_base[0] + b_plus[0] + b_prod[0];

    for (int grp = blockIdx.x; grp < nGroups; grp += gridDim.x) {
        int rowA = grp * GR + 2*wid;

        // stage x for both rows (coalesced float4), fold x . W_base on the fly
        const float4* xrA = (const float4*)(x + (size_t)rowA * MDIM);
        const float4* xrB = (const float4*)(x + (size_t)(rowA + 1) * MDIM);
        const float4* wb4 = (const float4*)W_base;
        float accA = 0.f, accB = 0.f;
        #pragma unroll
        for (int k = 0; k < MDIM/128; k++) {
            float4 a  = xrA[lane + 32*k];
            float4 b  = xrB[lane + 32*k];
            float4 wv = wb4[lane + 32*k];
            ((float4*)rbA)[lane + 32*k] = a;
            ((float4*)rbB)[lane + 32*k] = b;
            accA = fmaf(a.x, wv.x, fmaf(a.y, wv.y, fmaf(a.z, wv.z, fmaf(a.w, wv.w, accA))));
            accB = fmaf(b.x, wv.x, fmaf(b.y, wv.y, fmaf(b.z, wv.z, fmaf(b.w, wv.w, accB))));
        }
        __syncwarp();

        // level loop: stores contiguous at [s0,s1); next level prefetched and
        // UNPACKED to int registers before the syncwarp (off the chain).
        int s0 = 0;
        int s1 = offs[1];
        int ix, iy, iz, iw; float w0, w1, wz;
        if (lane < s1) {
            short4 q = sIdx[lane]; float4 ww = sWt[lane];
            ix = q.x; iy = q.y; iz = q.z; iw = q.w;
            w0 = ww.x; w1 = ww.y; wz = ww.z;
        }

        for (int L = 0; s0 < MDIM; L++) {
            int s2 = (int)offs[L + 2];
            int n = s1 - s0;
            if (lane < n) {                       // chunk 0 (prefetched)
                float a0A = rbA[ix], a1A = rbA[iy], b0A = rbA[iz], b1A = rbA[iw];
                float a0B = rbB[ix], a1B = rbB[iy], b0B = rbB[iz], b1B = rbB[iw];
                float tA = fmaf(w0, a0A, fmaf(w1, a1A, wz));
                float tB = fmaf(w0, a0B, fmaf(w1, a1B, wz));
                rbA[2*MDIM + s0 + lane] = b0A * b1A;          // prod (off chain)
                rbB[2*MDIM + s0 + lane] = b0B * b1B;
                rbA[MDIM   + s0 + lane] = sigmoid_fold(tA);   // plus
                rbB[MDIM   + s0 + lane] = sigmoid_fold(tB);
            }
            for (int cb = s0 + 32; cb < s1; cb += 32) {       // rare wide levels
                int sp = cb + lane;
                if (sp < s1) {
                    short4 q2 = sIdx[sp]; float4 w2 = sWt[sp];
                    int jx = q2.x, jy = q2.y, jz = q2.z, jw = q2.w;
                    float a0A = rbA[jx], a1A = rbA[jy], b0A = rbA[jz], b1A = rbA[jw];
                    float a0B = rbB[jx], a1B = rbB[jy], b0B = rbB[jz], b1B = rbB[jw];
                    float tA = fmaf(w2.x, a0A, fmaf(w2.y, a1A, w2.z));
                    float tB = fmaf(w2.x, a0B, fmaf(w2.y, a1B, w2.z));
                    rbA[2*MDIM + sp] = b0A * b1A;
                    rbB[2*MDIM + sp] = b0B * b1B;
                    rbA[MDIM   + sp] = sigmoid_fold(tA);
                    rbB[MDIM   + sp] = sigmoid_fold(tB);
                }
            }
            {   // prefetch + unpack next level chunk 0 (pre-sync, off chain)
                int sp = s1 + lane;
                if (sp < s2) {
                    short4 q = sIdx[sp]; float4 ww = sWt[sp];
                    ix = q.x; iy = q.y; iz = q.z; iw = q.w;
                    w0 = ww.x; w1 = ww.y; wz = ww.z;
                }
            }
            __syncwarp();
            s0 = s1; s1 = s2;
        }

        // epilogue: both rows' plus/prod dots with permuted weights
        for (int m = lane; m < MDIM; m += 32) {
            float2 we = wepi[m];
            accA = fmaf(rbA[MDIM + m], we.x, fmaf(rbA[2*MDIM + m], we.y, accA));
            accB = fmaf(rbB[MDIM + m], we.x, fmaf(rbB[2*MDIM + m], we.y, accB));
        }
        #pragma unroll
        for (int o = 16; o; o >>= 1) {
            accA += __shfl_xor_sync(0xffffffffu, accA, o);
            accB += __shfl_xor_sync(0xffffffffu, accB, o);
        }
        if (lane == 0) {
            out[rowA]     = accA + bias;
            out[rowA + 1] = accB + bias;
        }
        __syncwarp();
    }
}

// ---------------------------------------------------------------------------
extern "C" void kernel_launch(void* const* d_in, const int* in_sizes, int n_in,
                              void* d_out, int out_size) {
    const float* x  = (const float*)d_in[0];
    const int*   ri = (const int*)  d_in[1];
    const float* Wb = (const float*)d_in[2];
    const float* bb = (const float*)d_in[3];
    const float* Ws = (const float*)d_in[4];
    const float* bs = (const float*)d_in[5];
    const float* wp = (const float*)d_in[6];
    const float* bp = (const float*)d_in[7];
    const float* wq = (const float*)d_in[8];
    const float* bq = (const float*)d_in[9];
    float* out = (float*)d_out;

    int B = in_sizes[0] / MDIM;          // 8192
    int nGroups = B / GR;                // 512

    static int sm_count = 0;
    if (sm_count == 0) {
        int dev = 0;
        cudaGetDevice(&dev);
        cudaDeviceGetAttribute(&sm_count, cudaDevAttrMultiProcessorCount, dev);
        if (sm_count <= 0) sm_count = 148;
        cudaFuncSetAttribute(tree_kernel,
                             cudaFuncAttributeMaxDynamicSharedMemorySize, SMEM_BYTES);
    }
    int grid = nGroups < sm_count ? nGroups : sm_count;

    tree_kernel<<<grid, TPB, SMEM_BYTES>>>(x, ri, Wb, bb, Ws, bs, wp, bp, wq, bq,
                                           out, nGroups);
}